// round 15
// baseline (speedup 1.0000x reference)
#include <cuda_runtime.h>
#include <cuda_fp16.h>
#include <cstdint>

// Problem constants
#define BB 2
#define SS 2048
#define HH 16
#define HD 128
#define HID 2048
#define FF 8192
#define NTOK 4096

typedef __half hf;

// ---------------- scratch (device globals; no allocation allowed) ----------
__device__ float g_rope[SS * 16 * 2];
__device__ hf g_ln1[(size_t)NTOK * HID];
__device__ hf g_ln2[(size_t)NTOK * HID];
__device__ hf g_ctx[(size_t)NTOK * HID];
__device__ hf g_fc[(size_t)NTOK * FF];
__device__ hf g_Q[(size_t)NTOK * HID];
__device__ hf g_K[(size_t)NTOK * HID];
__device__ hf g_V[(size_t)NTOK * HID];
__device__ hf g_wqkv[(size_t)3 * HID * HID];
__device__ hf g_wo[(size_t)HID * HID];
__device__ hf g_wfc[(size_t)FF * HID];
__device__ hf g_wproj[(size_t)HID * FF];

// ---------------- helpers ----------------
__device__ __forceinline__ uint32_t smem_u32(const void* p) {
    uint32_t a;
    asm("{ .reg .u64 t; cvta.to.shared.u64 t, %1; cvt.u32.u64 %0, t; }" : "=r"(a) : "l"(p));
    return a;
}
#define CP16(dst, src) \
    asm volatile("cp.async.cg.shared.global [%0], [%1], 16;" :: "r"(dst), "l"(src) : "memory")
#define CP_COMMIT() asm volatile("cp.async.commit_group;" ::: "memory")
#define CP_WAIT1()  asm volatile("cp.async.wait_group 1;" ::: "memory")
#define CP_WAIT0()  asm volatile("cp.async.wait_group 0;" ::: "memory")

__device__ __forceinline__ void ldm_x4(uint32_t* r, uint32_t addr) {
    asm volatile("ldmatrix.sync.aligned.m8n8.x4.shared.b16 {%0,%1,%2,%3}, [%4];"
                 : "=r"(r[0]), "=r"(r[1]), "=r"(r[2]), "=r"(r[3]) : "r"(addr));
}
__device__ __forceinline__ void ldm_x4_t(uint32_t* r, uint32_t addr) {
    asm volatile("ldmatrix.sync.aligned.m8n8.x4.trans.shared.b16 {%0,%1,%2,%3}, [%4];"
                 : "=r"(r[0]), "=r"(r[1]), "=r"(r[2]), "=r"(r[3]) : "r"(addr));
}
__device__ __forceinline__ void mma_f16(float* c, const uint32_t* a, const uint32_t* b) {
    asm volatile("mma.sync.aligned.m16n8k16.row.col.f32.f16.f16.f32 "
                 "{%0,%1,%2,%3},{%4,%5,%6,%7},{%8,%9},{%0,%1,%2,%3};"
                 : "+f"(c[0]), "+f"(c[1]), "+f"(c[2]), "+f"(c[3])
                 : "r"(a[0]), "r"(a[1]), "r"(a[2]), "r"(a[3]), "r"(b[0]), "r"(b[1]));
}
__device__ __forceinline__ uint32_t pack_h(float a, float b) {
    __half2 hv;
    hv.x = __float2half_rn(a);
    hv.y = __float2half_rn(b);
    return *(uint32_t*)&hv;
}
__device__ __forceinline__ float gelu_exact(float v) {
    return 0.5f * v * (1.0f + erff(v * 0.70710678118654752f));
}

// ------- fused double layernorm (2 rows/block) + RoPE table ----------------
__global__ void ln_kernel(const float* __restrict__ x,
                          const float* __restrict__ g1, const float* __restrict__ b1,
                          const float* __restrict__ g2, const float* __restrict__ b2,
                          hf* __restrict__ o1, hf* __restrict__ o2,
                          float* __restrict__ rtab) {
    __shared__ float redS[16];
    __shared__ float redQ[16];
    const int t = threadIdx.x;             // 512
    const int half_ = t >> 8;
    const int tt = t & 255;
    const int row = blockIdx.x * 2 + half_;

    if (blockIdx.x < 64) {
        const int i = blockIdx.x * 512 + t;
        const int s = i >> 4, fi = i & 15;
        const float inv = powf(10000.0f, -(float)fi * (1.0f / 16.0f));
        float sn, cs;
        sincosf((float)s * inv, &sn, &cs);
        rtab[i * 2]     = cs;
        rtab[i * 2 + 1] = sn;
    }

    const float* xr = x + (size_t)row * HID;
    float4 a = *(const float4*)(xr + tt * 8);
    float4 b = *(const float4*)(xr + tt * 8 + 4);
    float s  = a.x + a.y + a.z + a.w + b.x + b.y + b.z + b.w;
    float ss = a.x*a.x + a.y*a.y + a.z*a.z + a.w*a.w
             + b.x*b.x + b.y*b.y + b.z*b.z + b.w*b.w;
    #pragma unroll
    for (int o = 16; o; o >>= 1) {
        s  += __shfl_xor_sync(0xffffffffu, s,  o);
        ss += __shfl_xor_sync(0xffffffffu, ss, o);
    }
    if ((t & 31) == 0) { redS[t >> 5] = s; redQ[t >> 5] = ss; }
    __syncthreads();
    s = 0.f; ss = 0.f;
    #pragma unroll
    for (int i = 0; i < 8; i++) { s += redS[half_ * 8 + i]; ss += redQ[half_ * 8 + i]; }
    const float mu  = s * (1.0f / HID);
    const float var = ss * (1.0f / HID) - mu * mu;
    const float rs  = rsqrtf(var + 1e-5f);

    float vals[8] = {a.x,a.y,a.z,a.w,b.x,b.y,b.z,b.w};
    __align__(16) hf h1[8], h2[8];
    #pragma unroll
    for (int q = 0; q < 8; q++) {
        const int col = tt * 8 + q;
        const float xn = (vals[q] - mu) * rs;
        h1[q] = __float2half_rn(xn * g1[col] + b1[col]);
        h2[q] = __float2half_rn(xn * g2[col] + b2[col]);
    }
    const size_t off = (size_t)row * HID + tt * 8;
    *(uint4*)(o1 + off) = *(uint4*)h1;
    *(uint4*)(o2 + off) = *(uint4*)h2;
}

// ------- weight convert + transpose (fp16): W[K][N] -> T[N][K] -------------
__global__ void wconv_h_kernel(const float* __restrict__ W, hf* __restrict__ Th,
                               int K, int N) {
    __shared__ float tile[64][65];
    const int n0 = blockIdx.x * 64, k0 = blockIdx.y * 64;
    const int tid = threadIdx.x;           // 256
    {
        const int r = tid >> 4, c = (tid & 15) * 4;
        #pragma unroll
        for (int i = 0; i < 4; i++) {
            const float4 v = *(const float4*)(W + (size_t)(k0 + r + 16 * i) * N + n0 + c);
            tile[r + 16 * i][c]     = v.x;
            tile[r + 16 * i][c + 1] = v.y;
            tile[r + 16 * i][c + 2] = v.z;
            tile[r + 16 * i][c + 3] = v.w;
        }
    }
    __syncthreads();
    #pragma unroll
    for (int it = 0; it < 2; ++it) {
        const int idx = tid + it * 256;
        const int n = idx >> 3, kc = (idx & 7) * 8;
        __align__(16) hf h[8];
        #pragma unroll
        for (int j = 0; j < 8; j++)
            h[j] = __float2half_rn(tile[kc + j][n]);
        const size_t o = (size_t)(n0 + n) * K + k0 + kc;
        *(uint4*)(Th + o) = *(uint4*)h;
    }
}

// ------- fp16 1-pass GEMM, CTA 256x128, BK=64, 512 thr, 3-stage pipe -------
#define ROWP   72
#define A_ARR  36864u
#define B_ARR  18432u
#define H_STG  (A_ARR + B_ARR)          // 55296
#define H_SMEM (3u * H_STG)             // 165888

// EPI: 1 gelu(+bias)->fp16 | 3 qkv fused | 4 +bias+add1->f32
template <int EPI>
__global__ void __launch_bounds__(512, 1) mma_gemm_h(
    const hf* __restrict__ A, const hf* __restrict__ B,
    const float* __restrict__ bias,
    const float* __restrict__ add1,
    const float* __restrict__ rtab,
    float* __restrict__ Cf, hf* __restrict__ Ch,
    hf* __restrict__ Ko, hf* __restrict__ Vo,
    int N, int K) {
    extern __shared__ char sm[];
    const uint32_t smb = smem_u32(sm);
    const int tid = threadIdx.x;
    const int lane = tid & 31;
    const int warp = tid >> 5;
    const int wm = warp >> 2;          // 4 warps along M (64 rows each)
    const int wn = warp & 3;           // 4 warps along N (32 cols each)

    const int Nt = N >> 7;
    const int pid = blockIdx.x;
    const int mt = (pid / (8 * Nt)) * 8 + (pid & 7);
    const int nt = (pid % (8 * Nt)) >> 3;

    const size_t arow0 = (size_t)mt * 256;
    const size_t brow0 = (size_t)nt * 128;
    const hf* pa = A + arow0 * K;
    const hf* pb = B + brow0 * K;
    const int nch = K >> 6;

    const uint32_t aoff = ((wm * 64 + (lane & 15)) * ROWP + (lane >> 4) * 8) * 2;
    const uint32_t boff = ((wn * 32 + (lane & 7) + ((lane >> 4) & 1) * 8) * ROWP
                           + ((lane >> 3) & 1) * 8) * 2;

    float acc[4][4][4];
    #pragma unroll
    for (int m = 0; m < 4; m++)
        #pragma unroll
        for (int n = 0; n < 4; n++)
            #pragma unroll
            for (int q = 0; q < 4; q++) acc[m][n][q] = 0.f;

    auto load_stage = [&](int stg, int k0) {
        const uint32_t sb = smb + (uint32_t)stg * H_STG;
        #pragma unroll
        for (int i = 0; i < 4; ++i) {       // A: 2048 16B chunks
            const int id = tid + i * 512;
            const int row = id >> 3, cc = id & 7;
            CP16(sb + (uint32_t)(row * ROWP + cc * 8) * 2,
                 pa + (size_t)row * K + k0 + cc * 8);
        }
        #pragma unroll
        for (int i = 0; i < 2; ++i) {       // B: 1024 chunks
            const int id = tid + i * 512;
            const int row = id >> 3, cc = id & 7;
            CP16(sb + A_ARR + (uint32_t)(row * ROWP + cc * 8) * 2,
                 pb + (size_t)row * K + k0 + cc * 8);
        }
    };

    // prolog: fill stages 0 and 1
    load_stage(0, 0);
    CP_COMMIT();
    load_stage(1, 64);
    CP_COMMIT();

    int stg = 0;
    for (int c = 0; c < nch; ++c) {
        if (c + 2 < nch) { CP_WAIT1(); } else { CP_WAIT0(); }
        __syncthreads();
        if (c + 2 < nch) {
            const int nstg = (stg + 2 >= 3) ? stg - 1 : stg + 2;
            load_stage(nstg, (c + 2) << 6);
            CP_COMMIT();
        }
        const uint32_t sb = smb + (uint32_t)stg * H_STG;
        #pragma unroll
        for (int ks = 0; ks < 4; ++ks) {
            const uint32_t kb = ks * 32;
            uint32_t ah[4][4], bh[2][4];
            #pragma unroll
            for (int i = 0; i < 4; ++i)
                ldm_x4(ah[i], sb + aoff + kb + i * 16 * ROWP * 2);
            #pragma unroll
            for (int t2 = 0; t2 < 2; ++t2)
                ldm_x4(bh[t2], sb + A_ARR + boff + kb + t2 * 16 * ROWP * 2);
            #pragma unroll
            for (int m = 0; m < 4; ++m)
                #pragma unroll
                for (int n = 0; n < 4; ++n)
                    mma_f16(acc[m][n], ah[m], &bh[n >> 1][(n & 1) * 2]);
        }
        stg = (stg + 1 == 3) ? 0 : stg + 1;
    }

    // ---------------- epilogue ----------------
    const int row_base = mt * 256 + wm * 64;
    const int col_base = nt * 128 + wn * 32;

    if (EPI == 3) {
        // qkv: bias, RoPE (d<32 of q/k), q-scale -> head-major fp16
        const int hh2 = col_base / 384;
        const int sub0 = col_base % 384;
        const int sect = sub0 >> 7;            // 0=q 1=k 2=v
        const int dbase = sub0 & 127;
        const bool ropeW = (dbase == 0) && (sect < 2);
        const float qsc = (sect == 0) ? 0.08838834764831845f : 1.0f;
        hf* Oo = (sect == 0) ? Ch : (sect == 1) ? Ko : Vo;
        #pragma unroll
        for (int m = 0; m < 4; ++m) {
            const int r0 = row_base + m * 16 + (lane >> 2);
            const int r1 = r0 + 8;
            const int bb2 = r0 >> 11;
            const int s0 = r0 & (SS - 1), s1 = r1 & (SS - 1);
            float v[4][4];
            #pragma unroll
            for (int n = 0; n < 4; ++n) {
                const int cc = col_base + n * 8 + (lane & 3) * 2;
                const float b0 = bias[cc], b1 = bias[cc + 1];
                v[n][0] = acc[m][n][0] + b0; v[n][1] = acc[m][n][1] + b1;
                v[n][2] = acc[m][n][2] + b0; v[n][3] = acc[m][n][3] + b1;
            }
            if (ropeW) {
                float rp[4][4];
                #pragma unroll
                for (int n = 0; n < 4; ++n) {
                    const int dl = n * 8 + (lane & 3) * 2;   // 0..30 even
                    const bool first = dl < 16;
                    const int np = first ? n + 2 : n - 2;
                    const float sign = first ? -1.0f : 1.0f;
                    const int fi0 = dl & 15, fi1 = (dl + 1) & 15;
                    const float2 c00 = *(const float2*)(rtab + (s0 * 16 + fi0) * 2);
                    const float2 c01 = *(const float2*)(rtab + (s0 * 16 + fi1) * 2);
                    const float2 c10 = *(const float2*)(rtab + (s1 * 16 + fi0) * 2);
                    const float2 c11 = *(const float2*)(rtab + (s1 * 16 + fi1) * 2);
                    rp[n][0] = v[n][0] * c00.x + sign * v[np][0] * c00.y;
                    rp[n][1] = v[n][1] * c01.x + sign * v[np][1] * c01.y;
                    rp[n][2] = v[n][2] * c10.x + sign * v[np][2] * c10.y;
                    rp[n][3] = v[n][3] * c11.x + sign * v[np][3] * c11.y;
                }
                #pragma unroll
                for (int n = 0; n < 4; ++n)
                    #pragma unroll
                    for (int q = 0; q < 4; ++q) v[n][q] = rp[n][q];
            }
            const size_t base0 = (((size_t)bb2 * HH + hh2) * SS + s0) * HD;
            const size_t base1 = (((size_t)bb2 * HH + hh2) * SS + s1) * HD;
            #pragma unroll
            for (int n = 0; n < 4; ++n) {
                const int d = dbase + n * 8 + (lane & 3) * 2;
                *(uint32_t*)(Oo + base0 + d) = pack_h(v[n][0] * qsc, v[n][1] * qsc);
                *(uint32_t*)(Oo + base1 + d) = pack_h(v[n][2] * qsc, v[n][3] * qsc);
            }
        }
        return;
    }

    #pragma unroll
    for (int m = 0; m < 4; ++m) {
        const int r0 = row_base + m * 16 + (lane >> 2);
        #pragma unroll
        for (int n = 0; n < 4; ++n) {
            const int cc = col_base + n * 8 + (lane & 3) * 2;
            const float b0 = bias[cc], b1 = bias[cc + 1];
            float v0 = acc[m][n][0] + b0, v1 = acc[m][n][1] + b1;
            float v2 = acc[m][n][2] + b0, v3 = acc[m][n][3] + b1;
            const size_t off0 = (size_t)r0 * N + cc;
            const size_t off1 = (size_t)(r0 + 8) * N + cc;
            if (EPI == 1) {
                *(uint32_t*)(Ch + off0) = pack_h(gelu_exact(v0), gelu_exact(v1));
                *(uint32_t*)(Ch + off1) = pack_h(gelu_exact(v2), gelu_exact(v3));
            } else {
                const float2 x0 = *(const float2*)(add1 + off0);
                const float2 x1 = *(const float2*)(add1 + off1);
                v0 += x0.x; v1 += x0.y;
                v2 += x1.x; v3 += x1.y;
                *(float2*)(Cf + off0) = make_float2(v0, v1);
                *(float2*)(Cf + off1) = make_float2(v2, v3);
            }
        }
    }
}

// ---------- causal flash attention, pure fp16, BQ=128 ----------------------
#define AST   136
#define ATILE (64 * AST * 2)
#define AQ_0  0
#define ASTAGE0 (2 * ATILE)              // Q is 128 rows = 2*ATILE
#define ASTG_B  (2 * ATILE)              // K, V
#define A_SMEM  (2 * ATILE + 2 * ASTG_B) // 104448

__global__ void __launch_bounds__(256, 1) attn_mma_kernel(
    const hf* __restrict__ Q, const hf* __restrict__ Kg,
    const hf* __restrict__ Vg,
    hf* __restrict__ ctx) {
    extern __shared__ char sm[];
    const uint32_t smb = smem_u32(sm);
    const int qt = gridDim.x - 1 - blockIdx.x;
    const int bhid = blockIdx.y;
    const int b = bhid >> 4, h = bhid & 15;
    const int tid = threadIdx.x;
    const int lane = tid & 31;
    const int w = tid >> 5;

    const size_t headbase = (size_t)bhid * SS * HD;

    auto ldq = [&]() {
        const size_t gb = headbase + (size_t)qt * 128 * HD;
        #pragma unroll
        for (int i = 0; i < 8; i++) {
            const int c = tid + i * 256;
            const int row = c >> 4, ch = c & 15;
            CP16(smb + AQ_0 + row * (AST * 2) + ch * 16,
                 Q + gb + (size_t)row * HD + ch * 8);
        }
    };
    auto ldkv = [&](int kt, int stg) {
        const uint32_t sb = smb + ASTAGE0 + (uint32_t)stg * ASTG_B;
        const size_t gb = headbase + (size_t)kt * 64 * HD;
        #pragma unroll
        for (int i = 0; i < 4; i++) {
            const int c = tid + i * 256;
            const int row = c >> 4, ch = c & 15;
            const uint32_t so = row * (AST * 2) + ch * 16;
            const size_t go = gb + (size_t)row * HD + ch * 8;
            CP16(sb + so,         Kg + go);
            CP16(sb + ATILE + so, Vg + go);
        }
    };

    const uint32_t qa_off = ((w * 16 + (lane & 15)) * AST + (lane >> 4) * 8) * 2;
    const int lm = lane >> 3, li = lane & 7;
    const uint32_t kb_off = (((lm >> 1) * 8 + li) * AST + (lm & 1) * 8) * 2;
    const uint32_t vb_off = (((lm & 1) * 8 + li) * AST + (lm >> 1) * 8) * 2;

    float oacc[16][4];
    #pragma unroll
    for (int t = 0; t < 16; t++)
        #pragma unroll
        for (int q = 0; q < 4; q++) oacc[t][q] = 0.f;
    float m0 = -1e30f, m1 = -1e30f, l0 = 0.f, l1 = 0.f;
    const int qrow0 = qt * 128 + w * 16 + (lane >> 2);
    const int qrow1 = qrow0 + 8;
    const int nkt = 2 * qt + 2;

    ldq();
    ldkv(0, 0);
    CP_COMMIT();

    for (int kt = 0; kt < nkt; ++kt) {
        if (kt + 1 < nkt) {
            ldkv(kt + 1, (kt + 1) & 1);
            CP_COMMIT();
            CP_WAIT1();
        } else {
            CP_WAIT0();
        }
        __syncthreads();
        const uint32_t sb = smb + ASTAGE0 + (uint32_t)(kt & 1) * ASTG_B;

        float sacc[8][4];
        #pragma unroll
        for (int j = 0; j < 8; j++)
            #pragma unroll
            for (int q = 0; q < 4; q++) sacc[j][q] = 0.f;

        #pragma unroll
        for (int ks = 0; ks < 8; ++ks) {
            uint32_t ah[4], kfh[8][2];
            ldm_x4(ah, smb + AQ_0 + qa_off + ks * 32);
            #pragma unroll
            for (int jp = 0; jp < 4; ++jp) {
                uint32_t r[4];
                ldm_x4(r, sb + kb_off + (jp * 16 * AST + ks * 16) * 2);
                kfh[2*jp][0] = r[0]; kfh[2*jp][1] = r[1];
                kfh[2*jp+1][0] = r[2]; kfh[2*jp+1][1] = r[3];
            }
            #pragma unroll
            for (int j = 0; j < 8; ++j) mma_f16(sacc[j], ah, kfh[j]);
        }

        if (kt >= 2 * qt) {
            #pragma unroll
            for (int j = 0; j < 8; ++j) {
                const int c0 = kt * 64 + j * 8 + (lane & 3) * 2;
                if (c0     > qrow0) sacc[j][0] = -1e30f;
                if (c0 + 1 > qrow0) sacc[j][1] = -1e30f;
                if (c0     > qrow1) sacc[j][2] = -1e30f;
                if (c0 + 1 > qrow1) sacc[j][3] = -1e30f;
            }
        }

        float mx0 = -1e30f, mx1 = -1e30f;
        #pragma unroll
        for (int j = 0; j < 8; ++j) {
            mx0 = fmaxf(mx0, fmaxf(sacc[j][0], sacc[j][1]));
            mx1 = fmaxf(mx1, fmaxf(sacc[j][2], sacc[j][3]));
        }
        #pragma unroll
        for (int o = 1; o < 4; o <<= 1) {
            mx0 = fmaxf(mx0, __shfl_xor_sync(0xffffffffu, mx0, o));
            mx1 = fmaxf(mx1, __shfl_xor_sync(0xffffffffu, mx1, o));
        }
        const float mn0 = fmaxf(m0, mx0), mn1 = fmaxf(m1, mx1);
        const float e0 = __expf(m0 - mn0), e1 = __expf(m1 - mn1);
        m0 = mn0; m1 = mn1;
        float rs0 = 0.f, rs1 = 0.f;
        #pragma unroll
        for (int j = 0; j < 8; ++j) {
            sacc[j][0] = __expf(sacc[j][0] - mn0); rs0 += sacc[j][0];
            sacc[j][1] = __expf(sacc[j][1] - mn0); rs0 += sacc[j][1];
            sacc[j][2] = __expf(sacc[j][2] - mn1); rs1 += sacc[j][2];
            sacc[j][3] = __expf(sacc[j][3] - mn1); rs1 += sacc[j][3];
        }
        #pragma unroll
        for (int o = 1; o < 4; o <<= 1) {
            rs0 += __shfl_xor_sync(0xffffffffu, rs0, o);
            rs1 += __shfl_xor_sync(0xffffffffu, rs1, o);
        }
        l0 = l0 * e0 + rs0;
        l1 = l1 * e1 + rs1;
        #pragma unroll
        for (int t = 0; t < 16; t++) {
            oacc[t][0] *= e0; oacc[t][1] *= e0;
            oacc[t][2] *= e1; oacc[t][3] *= e1;
        }

        #pragma unroll
        for (int c = 0; c < 4; ++c) {
            uint32_t pah[4];
            pah[0] = pack_h(sacc[2*c][0],   sacc[2*c][1]);
            pah[1] = pack_h(sacc[2*c][2],   sacc[2*c][3]);
            pah[2] = pack_h(sacc[2*c+1][0], sacc[2*c+1][1]);
            pah[3] = pack_h(sacc[2*c+1][2], sacc[2*c+1][3]);
            #pragma unroll
            for (int tp = 0; tp < 8; ++tp) {
                uint32_t rvh[4];
                ldm_x4_t(rvh, sb + ATILE + vb_off + (c * 16 * AST + tp * 16) * 2);
                mma_f16(oacc[2*tp],   pah, &rvh[0]);
                mma_f16(oacc[2*tp+1], pah, &rvh[2]);
            }
        }
        __syncthreads();
    }

    const float inv0 = 1.0f / l0, inv1 = 1.0f / l1;
    const size_t ob0 = ((size_t)b * SS + qrow0) * HID + h * HD;
    const size_t ob1 = ((size_t)b * SS + qrow1) * HID + h * HD;
    #pragma unroll
    for (int t = 0; t < 16; ++t) {
        const int d = t * 8 + (lane & 3) * 2;
        *(uint32_t*)(ctx + ob0 + d) = pack_h(oacc[t][0] * inv0, oacc[t][1] * inv0);
        *(uint32_t*)(ctx + ob1 + d) = pack_h(oacc[t][2] * inv1, oacc[t][3] * inv1);
    }
}

// ---------------- launch (dense stream DAG; Wo last) ----------------
extern "C" void kernel_launch(void* const* d_in, const int* in_sizes, int n_in,
                              void* d_out, int out_size) {
    const float* hid   = (const float*)d_in[0];
    const float* ln1g  = (const float*)d_in[1];
    const float* ln1b  = (const float*)d_in[2];
    const float* ln2g  = (const float*)d_in[3];
    const float* ln2b  = (const float*)d_in[4];
    const float* Wqkv  = (const float*)d_in[5];
    const float* bqkv  = (const float*)d_in[6];
    const float* Wo    = (const float*)d_in[7];
    const float* bo    = (const float*)d_in[8];
    const float* Wfc   = (const float*)d_in[9];
    const float* bfc   = (const float*)d_in[10];
    const float* Wproj = (const float*)d_in[11];
    const float* bproj = (const float*)d_in[12];
    float* out = (float*)d_out;

    float *rope;
    hf *ln1, *ln2, *ctx, *fc, *Q, *K, *V;
    hf *wqkv, *wo, *wfc, *wproj;
    cudaGetSymbolAddress((void**)&rope, g_rope);
    cudaGetSymbolAddress((void**)&ln1, g_ln1);
    cudaGetSymbolAddress((void**)&ln2, g_ln2);
    cudaGetSymbolAddress((void**)&ctx, g_ctx);
    cudaGetSymbolAddress((void**)&fc, g_fc);
    cudaGetSymbolAddress((void**)&Q, g_Q);
    cudaGetSymbolAddress((void**)&K, g_K);
    cudaGetSymbolAddress((void**)&V, g_V);
    cudaGetSymbolAddress((void**)&wqkv, g_wqkv);
    cudaGetSymbolAddress((void**)&wo, g_wo);
    cudaGetSymbolAddress((void**)&wfc, g_wfc);
    cudaGetSymbolAddress((void**)&wproj, g_wproj);

    cudaFuncSetAttribute(mma_gemm_h<1>, cudaFuncAttributeMaxDynamicSharedMemorySize, H_SMEM);
    cudaFuncSetAttribute(mma_gemm_h<3>, cudaFuncAttributeMaxDynamicSharedMemorySize, H_SMEM);
    cudaFuncSetAttribute(mma_gemm_h<4>, cudaFuncAttributeMaxDynamicSharedMemorySize, H_SMEM);
    cudaFuncSetAttribute(attn_mma_kernel, cudaFuncAttributeMaxDynamicSharedMemorySize, A_SMEM);

    static cudaStream_t sB = nullptr, sC = nullptr;
    static cudaEvent_t evRoot = nullptr, evLn = nullptr, evWq = nullptr,
                       evWo = nullptr, evWp = nullptr, evPROJ = nullptr;
    if (!sB) {
        cudaStreamCreateWithFlags(&sB, cudaStreamNonBlocking);
        cudaStreamCreateWithFlags(&sC, cudaStreamNonBlocking);
        cudaEventCreateWithFlags(&evRoot, cudaEventDisableTiming);
        cudaEventCreateWithFlags(&evLn,   cudaEventDisableTiming);
        cudaEventCreateWithFlags(&evWq,   cudaEventDisableTiming);
        cudaEventCreateWithFlags(&evWo,   cudaEventDisableTiming);
        cudaEventCreateWithFlags(&evWp,   cudaEventDisableTiming);
        cudaEventCreateWithFlags(&evPROJ, cudaEventDisableTiming);
    }

    cudaEventRecord(evRoot, 0);
    cudaStreamWaitEvent(sB, evRoot, 0);
    cudaStreamWaitEvent(sC, evRoot, 0);

    // --- stream C: Wqkv, Wo, Wproj conversions ---
    wconv_h_kernel<<<dim3(3 * HID / 64, HID / 64), 256, 0, sC>>>(Wqkv, wqkv, HID, 3 * HID);
    cudaEventRecord(evWq, sC);
    wconv_h_kernel<<<dim3(HID / 64, HID / 64), 256, 0, sC>>>(Wo, wo, HID, HID);
    cudaEventRecord(evWo, sC);
    wconv_h_kernel<<<dim3(HID / 64, FF / 64), 256, 0, sC>>>(Wproj, wproj, FF, HID);
    cudaEventRecord(evWp, sC);

    // --- stream B: Wfc conversion, FC gemm, PROJ gemm ---
    wconv_h_kernel<<<dim3(FF / 64, HID / 64), 256, 0, sB>>>(Wfc, wfc, HID, FF);

    // --- origin: ln (+rope table) ---
    ln_kernel<<<NTOK / 2, 512>>>(hid, ln1g, ln1b, ln2g, ln2b, ln1, ln2, rope);
    cudaEventRecord(evLn, 0);

    // stream B: FC = gelu(ln2 @ W_fc + b_fc)
    cudaStreamWaitEvent(sB, evLn, 0);
    mma_gemm_h<1><<<16 * (FF / 128), 512, H_SMEM, sB>>>(
        ln2, wfc, bfc, nullptr, nullptr,
        nullptr, fc, nullptr, nullptr, FF, HID);
    // stream B: out = fc @ W_proj + b_proj + hid
    cudaStreamWaitEvent(sB, evWp, 0);
    mma_gemm_h<4><<<16 * (HID / 128), 512, H_SMEM, sB>>>(
        fc, wproj, bproj, hid, nullptr,
        out, nullptr, nullptr, nullptr, HID, FF);
    cudaEventRecord(evPROJ, sB);

    // origin: QKV gemm + fused bias/RoPE/scale/head-transpose
    cudaStreamWaitEvent(0, evWq, 0);
    mma_gemm_h<3><<<16 * (3 * HID / 128), 512, H_SMEM>>>(
        ln1, wqkv, bqkv, nullptr, rope,
        nullptr, Q, K, V, 3 * HID, HID);

    // origin: attention (pure fp16)
    attn_mma_kernel<<<dim3(SS / 128, BB * HH), 256, A_SMEM>>>(Q, K, V, ctx);

    // origin: out += ctx @ W_o + b_o
    cudaStreamWaitEvent(0, evWo, 0);
    cudaStreamWaitEvent(0, evPROJ, 0);
    mma_gemm_h<4><<<16 * (HID / 128), 512, H_SMEM>>>(
        ctx, wo, bo, out, nullptr,
        out, nullptr, nullptr, nullptr, HID, HID);
}

// round 16
// speedup vs baseline: 1.0190x; 1.0190x over previous
#include <cuda_runtime.h>
#include <cuda_fp16.h>
#include <cstdint>

// Problem constants
#define BB 2
#define SS 2048
#define HH 16
#define HD 128
#define HID 2048
#define FF 8192
#define NTOK 4096

typedef __half hf;

// ---------------- scratch (device globals; no allocation allowed) ----------
__device__ float g_rope[SS * 16 * 2];
__device__ hf g_ln1[(size_t)NTOK * HID];
__device__ hf g_ln2[(size_t)NTOK * HID];
__device__ hf g_ctx[(size_t)NTOK * HID];
__device__ hf g_fc[(size_t)NTOK * FF];
__device__ hf g_Q[(size_t)NTOK * HID];
__device__ hf g_K[(size_t)NTOK * HID];
__device__ hf g_V[(size_t)NTOK * HID];
__device__ hf g_wqkv[(size_t)3 * HID * HID];
__device__ hf g_wo[(size_t)HID * HID];
__device__ hf g_wfc[(size_t)FF * HID];
__device__ hf g_wproj[(size_t)HID * FF];

// ---------------- helpers ----------------
__device__ __forceinline__ uint32_t smem_u32(const void* p) {
    uint32_t a;
    asm("{ .reg .u64 t; cvta.to.shared.u64 t, %1; cvt.u32.u64 %0, t; }" : "=r"(a) : "l"(p));
    return a;
}
#define CP16(dst, src) \
    asm volatile("cp.async.cg.shared.global [%0], [%1], 16;" :: "r"(dst), "l"(src) : "memory")
#define CP_COMMIT() asm volatile("cp.async.commit_group;" ::: "memory")
#define CP_WAIT1()  asm volatile("cp.async.wait_group 1;" ::: "memory")
#define CP_WAIT0()  asm volatile("cp.async.wait_group 0;" ::: "memory")

__device__ __forceinline__ void ldm_x4(uint32_t* r, uint32_t addr) {
    asm volatile("ldmatrix.sync.aligned.m8n8.x4.shared.b16 {%0,%1,%2,%3}, [%4];"
                 : "=r"(r[0]), "=r"(r[1]), "=r"(r[2]), "=r"(r[3]) : "r"(addr));
}
__device__ __forceinline__ void ldm_x4_t(uint32_t* r, uint32_t addr) {
    asm volatile("ldmatrix.sync.aligned.m8n8.x4.trans.shared.b16 {%0,%1,%2,%3}, [%4];"
                 : "=r"(r[0]), "=r"(r[1]), "=r"(r[2]), "=r"(r[3]) : "r"(addr));
}
__device__ __forceinline__ void mma_f16(float* c, const uint32_t* a, const uint32_t* b) {
    asm volatile("mma.sync.aligned.m16n8k16.row.col.f32.f16.f16.f32 "
                 "{%0,%1,%2,%3},{%4,%5,%6,%7},{%8,%9},{%0,%1,%2,%3};"
                 : "+f"(c[0]), "+f"(c[1]), "+f"(c[2]), "+f"(c[3])
                 : "r"(a[0]), "r"(a[1]), "r"(a[2]), "r"(a[3]), "r"(b[0]), "r"(b[1]));
}
__device__ __forceinline__ uint32_t pack_h(float a, float b) {
    __half2 hv;
    hv.x = __float2half_rn(a);
    hv.y = __float2half_rn(b);
    return *(uint32_t*)&hv;
}
__device__ __forceinline__ float gelu_exact(float v) {
    return 0.5f * v * (1.0f + erff(v * 0.70710678118654752f));
}

// ------- fused double layernorm (2 rows/block) + RoPE table ----------------
__global__ void ln_kernel(const float* __restrict__ x,
                          const float* __restrict__ g1, const float* __restrict__ b1,
                          const float* __restrict__ g2, const float* __restrict__ b2,
                          hf* __restrict__ o1, hf* __restrict__ o2,
                          float* __restrict__ rtab) {
    __shared__ float redS[16];
    __shared__ float redQ[16];
    const int t = threadIdx.x;             // 512
    const int half_ = t >> 8;
    const int tt = t & 255;
    const int row = blockIdx.x * 2 + half_;

    if (blockIdx.x < 64) {
        const int i = blockIdx.x * 512 + t;
        const int s = i >> 4, fi = i & 15;
        const float inv = powf(10000.0f, -(float)fi * (1.0f / 16.0f));
        float sn, cs;
        sincosf((float)s * inv, &sn, &cs);
        rtab[i * 2]     = cs;
        rtab[i * 2 + 1] = sn;
    }

    const float* xr = x + (size_t)row * HID;
    float4 a = *(const float4*)(xr + tt * 8);
    float4 b = *(const float4*)(xr + tt * 8 + 4);
    float s  = a.x + a.y + a.z + a.w + b.x + b.y + b.z + b.w;
    float ss = a.x*a.x + a.y*a.y + a.z*a.z + a.w*a.w
             + b.x*b.x + b.y*b.y + b.z*b.z + b.w*b.w;
    #pragma unroll
    for (int o = 16; o; o >>= 1) {
        s  += __shfl_xor_sync(0xffffffffu, s,  o);
        ss += __shfl_xor_sync(0xffffffffu, ss, o);
    }
    if ((t & 31) == 0) { redS[t >> 5] = s; redQ[t >> 5] = ss; }
    __syncthreads();
    s = 0.f; ss = 0.f;
    #pragma unroll
    for (int i = 0; i < 8; i++) { s += redS[half_ * 8 + i]; ss += redQ[half_ * 8 + i]; }
    const float mu  = s * (1.0f / HID);
    const float var = ss * (1.0f / HID) - mu * mu;
    const float rs  = rsqrtf(var + 1e-5f);

    float vals[8] = {a.x,a.y,a.z,a.w,b.x,b.y,b.z,b.w};
    __align__(16) hf h1[8], h2[8];
    #pragma unroll
    for (int q = 0; q < 8; q++) {
        const int col = tt * 8 + q;
        const float xn = (vals[q] - mu) * rs;
        h1[q] = __float2half_rn(xn * g1[col] + b1[col]);
        h2[q] = __float2half_rn(xn * g2[col] + b2[col]);
    }
    const size_t off = (size_t)row * HID + tt * 8;
    *(uint4*)(o1 + off) = *(uint4*)h1;
    *(uint4*)(o2 + off) = *(uint4*)h2;
}

// ------- weight convert + transpose (fp16): W[K][N] -> T[N][K] -------------
__global__ void wconv_h_kernel(const float* __restrict__ W, hf* __restrict__ Th,
                               int K, int N) {
    __shared__ float tile[64][65];
    const int n0 = blockIdx.x * 64, k0 = blockIdx.y * 64;
    const int tid = threadIdx.x;           // 256
    {
        const int r = tid >> 4, c = (tid & 15) * 4;
        #pragma unroll
        for (int i = 0; i < 4; i++) {
            const float4 v = *(const float4*)(W + (size_t)(k0 + r + 16 * i) * N + n0 + c);
            tile[r + 16 * i][c]     = v.x;
            tile[r + 16 * i][c + 1] = v.y;
            tile[r + 16 * i][c + 2] = v.z;
            tile[r + 16 * i][c + 3] = v.w;
        }
    }
    __syncthreads();
    #pragma unroll
    for (int it = 0; it < 2; ++it) {
        const int idx = tid + it * 256;
        const int n = idx >> 3, kc = (idx & 7) * 8;
        __align__(16) hf h[8];
        #pragma unroll
        for (int j = 0; j < 8; j++)
            h[j] = __float2half_rn(tile[kc + j][n]);
        const size_t o = (size_t)(n0 + n) * K + k0 + kc;
        *(uint4*)(Th + o) = *(uint4*)h;
    }
}

// ------- fp16 1-pass GEMM, CTA 256x128, BK=128, 512 thr, 2-stage -----------
#define ROWP   136
#define A_ARR  69632u
#define B_ARR  34816u
#define H_STG  (A_ARR + B_ARR)          // 104448
#define H_SMEM (2u * H_STG)             // 208896

// EPI: 1 gelu(+bias)->fp16 | 3 qkv fused | 4 +bias+add1->f32
template <int EPI>
__global__ void __launch_bounds__(512, 1) mma_gemm_h(
    const hf* __restrict__ A, const hf* __restrict__ B,
    const float* __restrict__ bias,
    const float* __restrict__ add1,
    const float* __restrict__ rtab,
    float* __restrict__ Cf, hf* __restrict__ Ch,
    hf* __restrict__ Ko, hf* __restrict__ Vo,
    int N, int K) {
    extern __shared__ char sm[];
    const uint32_t smb = smem_u32(sm);
    const int tid = threadIdx.x;
    const int lane = tid & 31;
    const int warp = tid >> 5;
    const int wm = warp >> 2;          // 4 warps along M (64 rows each)
    const int wn = warp & 3;           // 4 warps along N (32 cols each)

    const int Nt = N >> 7;
    const int pid = blockIdx.x;
    const int mt = (pid / (8 * Nt)) * 8 + (pid & 7);
    const int nt = (pid % (8 * Nt)) >> 3;

    const size_t arow0 = (size_t)mt * 256;
    const size_t brow0 = (size_t)nt * 128;
    const hf* pa = A + arow0 * K;
    const hf* pb = B + brow0 * K;
    const int nch = K >> 7;

    const uint32_t aoff = ((wm * 64 + (lane & 15)) * ROWP + (lane >> 4) * 8) * 2;
    const uint32_t boff = ((wn * 32 + (lane & 7) + ((lane >> 4) & 1) * 8) * ROWP
                           + ((lane >> 3) & 1) * 8) * 2;

    float acc[4][4][4];
    #pragma unroll
    for (int m = 0; m < 4; m++)
        #pragma unroll
        for (int n = 0; n < 4; n++)
            #pragma unroll
            for (int q = 0; q < 4; q++) acc[m][n][q] = 0.f;

    auto load_stage = [&](int stg, int k0) {
        const uint32_t sb = smb + (uint32_t)stg * H_STG;
        #pragma unroll
        for (int i = 0; i < 8; ++i) {       // A: 4096 16B chunks (256r x 16c)
            const int id = tid + i * 512;
            const int row = id >> 4, cc = id & 15;
            CP16(sb + (uint32_t)(row * ROWP + cc * 8) * 2,
                 pa + (size_t)row * K + k0 + cc * 8);
        }
        #pragma unroll
        for (int i = 0; i < 4; ++i) {       // B: 2048 chunks (128r x 16c)
            const int id = tid + i * 512;
            const int row = id >> 4, cc = id & 15;
            CP16(sb + A_ARR + (uint32_t)(row * ROWP + cc * 8) * 2,
                 pb + (size_t)row * K + k0 + cc * 8);
        }
    };

    load_stage(0, 0);
    CP_COMMIT();

    for (int c = 0; c < nch; ++c) {
        CP_WAIT0();
        __syncthreads();
        if (c + 1 < nch) {
            load_stage((c + 1) & 1, (c + 1) << 7);
            CP_COMMIT();
        }
        const uint32_t sb = smb + (uint32_t)(c & 1) * H_STG;
        #pragma unroll
        for (int ks = 0; ks < 8; ++ks) {
            const uint32_t kb = ks * 32;
            uint32_t ah[4][4], bh[2][4];
            #pragma unroll
            for (int i = 0; i < 4; ++i)
                ldm_x4(ah[i], sb + aoff + kb + i * 16 * ROWP * 2);
            #pragma unroll
            for (int t2 = 0; t2 < 2; ++t2)
                ldm_x4(bh[t2], sb + A_ARR + boff + kb + t2 * 16 * ROWP * 2);
            #pragma unroll
            for (int m = 0; m < 4; ++m)
                #pragma unroll
                for (int n = 0; n < 4; ++n)
                    mma_f16(acc[m][n], ah[m], &bh[n >> 1][(n & 1) * 2]);
        }
    }

    // ---------------- epilogue ----------------
    const int row_base = mt * 256 + wm * 64;
    const int col_base = nt * 128 + wn * 32;

    if (EPI == 3) {
        // qkv: bias, RoPE (d<32 of q/k), q-scale -> head-major fp16
        const int hh2 = col_base / 384;
        const int sub0 = col_base % 384;
        const int sect = sub0 >> 7;            // 0=q 1=k 2=v
        const int dbase = sub0 & 127;
        const bool ropeW = (dbase == 0) && (sect < 2);
        const float qsc = (sect == 0) ? 0.08838834764831845f : 1.0f;
        hf* Oo = (sect == 0) ? Ch : (sect == 1) ? Ko : Vo;
        #pragma unroll
        for (int m = 0; m < 4; ++m) {
            const int r0 = row_base + m * 16 + (lane >> 2);
            const int r1 = r0 + 8;
            const int bb2 = r0 >> 11;
            const int s0 = r0 & (SS - 1), s1 = r1 & (SS - 1);
            float v[4][4];
            #pragma unroll
            for (int n = 0; n < 4; ++n) {
                const int cc = col_base + n * 8 + (lane & 3) * 2;
                const float b0 = bias[cc], b1 = bias[cc + 1];
                v[n][0] = acc[m][n][0] + b0; v[n][1] = acc[m][n][1] + b1;
                v[n][2] = acc[m][n][2] + b0; v[n][3] = acc[m][n][3] + b1;
            }
            if (ropeW) {
                float rp[4][4];
                #pragma unroll
                for (int n = 0; n < 4; ++n) {
                    const int dl = n * 8 + (lane & 3) * 2;   // 0..30 even
                    const bool first = dl < 16;
                    const int np = first ? n + 2 : n - 2;
                    const float sign = first ? -1.0f : 1.0f;
                    const int fi0 = dl & 15, fi1 = (dl + 1) & 15;
                    const float2 c00 = *(const float2*)(rtab + (s0 * 16 + fi0) * 2);
                    const float2 c01 = *(const float2*)(rtab + (s0 * 16 + fi1) * 2);
                    const float2 c10 = *(const float2*)(rtab + (s1 * 16 + fi0) * 2);
                    const float2 c11 = *(const float2*)(rtab + (s1 * 16 + fi1) * 2);
                    rp[n][0] = v[n][0] * c00.x + sign * v[np][0] * c00.y;
                    rp[n][1] = v[n][1] * c01.x + sign * v[np][1] * c01.y;
                    rp[n][2] = v[n][2] * c10.x + sign * v[np][2] * c10.y;
                    rp[n][3] = v[n][3] * c11.x + sign * v[np][3] * c11.y;
                }
                #pragma unroll
                for (int n = 0; n < 4; ++n)
                    #pragma unroll
                    for (int q = 0; q < 4; ++q) v[n][q] = rp[n][q];
            }
            const size_t base0 = (((size_t)bb2 * HH + hh2) * SS + s0) * HD;
            const size_t base1 = (((size_t)bb2 * HH + hh2) * SS + s1) * HD;
            #pragma unroll
            for (int n = 0; n < 4; ++n) {
                const int d = dbase + n * 8 + (lane & 3) * 2;
                *(uint32_t*)(Oo + base0 + d) = pack_h(v[n][0] * qsc, v[n][1] * qsc);
                *(uint32_t*)(Oo + base1 + d) = pack_h(v[n][2] * qsc, v[n][3] * qsc);
            }
        }
        return;
    }

    #pragma unroll
    for (int m = 0; m < 4; ++m) {
        const int r0 = row_base + m * 16 + (lane >> 2);
        #pragma unroll
        for (int n = 0; n < 4; ++n) {
            const int cc = col_base + n * 8 + (lane & 3) * 2;
            const float b0 = bias[cc], b1 = bias[cc + 1];
            float v0 = acc[m][n][0] + b0, v1 = acc[m][n][1] + b1;
            float v2 = acc[m][n][2] + b0, v3 = acc[m][n][3] + b1;
            const size_t off0 = (size_t)r0 * N + cc;
            const size_t off1 = (size_t)(r0 + 8) * N + cc;
            if (EPI == 1) {
                *(uint32_t*)(Ch + off0) = pack_h(gelu_exact(v0), gelu_exact(v1));
                *(uint32_t*)(Ch + off1) = pack_h(gelu_exact(v2), gelu_exact(v3));
            } else {
                const float2 x0 = *(const float2*)(add1 + off0);
                const float2 x1 = *(const float2*)(add1 + off1);
                v0 += x0.x; v1 += x0.y;
                v2 += x1.x; v3 += x1.y;
                *(float2*)(Cf + off0) = make_float2(v0, v1);
                *(float2*)(Cf + off1) = make_float2(v2, v3);
            }
        }
    }
}

// ---------- causal flash attention, pure fp16, BQ=128 ----------------------
#define AST   136
#define ATILE (64 * AST * 2)
#define AQ_0  0
#define ASTAGE0 (2 * ATILE)              // Q is 128 rows = 2*ATILE
#define ASTG_B  (2 * ATILE)              // K, V
#define A_SMEM  (2 * ATILE + 2 * ASTG_B) // 104448

__global__ void __launch_bounds__(256, 1) attn_mma_kernel(
    const hf* __restrict__ Q, const hf* __restrict__ Kg,
    const hf* __restrict__ Vg,
    hf* __restrict__ ctx) {
    extern __shared__ char sm[];
    const uint32_t smb = smem_u32(sm);
    const int qt = gridDim.x - 1 - blockIdx.x;
    const int bhid = blockIdx.y;
    const int b = bhid >> 4, h = bhid & 15;
    const int tid = threadIdx.x;
    const int lane = tid & 31;
    const int w = tid >> 5;

    const size_t headbase = (size_t)bhid * SS * HD;

    auto ldq = [&]() {
        const size_t gb = headbase + (size_t)qt * 128 * HD;
        #pragma unroll
        for (int i = 0; i < 8; i++) {
            const int c = tid + i * 256;
            const int row = c >> 4, ch = c & 15;
            CP16(smb + AQ_0 + row * (AST * 2) + ch * 16,
                 Q + gb + (size_t)row * HD + ch * 8);
        }
    };
    auto ldkv = [&](int kt, int stg) {
        const uint32_t sb = smb + ASTAGE0 + (uint32_t)stg * ASTG_B;
        const size_t gb = headbase + (size_t)kt * 64 * HD;
        #pragma unroll
        for (int i = 0; i < 4; i++) {
            const int c = tid + i * 256;
            const int row = c >> 4, ch = c & 15;
            const uint32_t so = row * (AST * 2) + ch * 16;
            const size_t go = gb + (size_t)row * HD + ch * 8;
            CP16(sb + so,         Kg + go);
            CP16(sb + ATILE + so, Vg + go);
        }
    };

    const uint32_t qa_off = ((w * 16 + (lane & 15)) * AST + (lane >> 4) * 8) * 2;
    const int lm = lane >> 3, li = lane & 7;
    const uint32_t kb_off = (((lm >> 1) * 8 + li) * AST + (lm & 1) * 8) * 2;
    const uint32_t vb_off = (((lm & 1) * 8 + li) * AST + (lm >> 1) * 8) * 2;

    float oacc[16][4];
    #pragma unroll
    for (int t = 0; t < 16; t++)
        #pragma unroll
        for (int q = 0; q < 4; q++) oacc[t][q] = 0.f;
    float m0 = -1e30f, m1 = -1e30f, l0 = 0.f, l1 = 0.f;
    const int qrow0 = qt * 128 + w * 16 + (lane >> 2);
    const int qrow1 = qrow0 + 8;
    const int nkt = 2 * qt + 2;

    ldq();
    ldkv(0, 0);
    CP_COMMIT();

    for (int kt = 0; kt < nkt; ++kt) {
        if (kt + 1 < nkt) {
            ldkv(kt + 1, (kt + 1) & 1);
            CP_COMMIT();
            CP_WAIT1();
        } else {
            CP_WAIT0();
        }
        __syncthreads();
        const uint32_t sb = smb + ASTAGE0 + (uint32_t)(kt & 1) * ASTG_B;

        float sacc[8][4];
        #pragma unroll
        for (int j = 0; j < 8; j++)
            #pragma unroll
            for (int q = 0; q < 4; q++) sacc[j][q] = 0.f;

        #pragma unroll
        for (int ks = 0; ks < 8; ++ks) {
            uint32_t ah[4], kfh[8][2];
            ldm_x4(ah, smb + AQ_0 + qa_off + ks * 32);
            #pragma unroll
            for (int jp = 0; jp < 4; ++jp) {
                uint32_t r[4];
                ldm_x4(r, sb + kb_off + (jp * 16 * AST + ks * 16) * 2);
                kfh[2*jp][0] = r[0]; kfh[2*jp][1] = r[1];
                kfh[2*jp+1][0] = r[2]; kfh[2*jp+1][1] = r[3];
            }
            #pragma unroll
            for (int j = 0; j < 8; ++j) mma_f16(sacc[j], ah, kfh[j]);
        }

        if (kt >= 2 * qt) {
            #pragma unroll
            for (int j = 0; j < 8; ++j) {
                const int c0 = kt * 64 + j * 8 + (lane & 3) * 2;
                if (c0     > qrow0) sacc[j][0] = -1e30f;
                if (c0 + 1 > qrow0) sacc[j][1] = -1e30f;
                if (c0     > qrow1) sacc[j][2] = -1e30f;
                if (c0 + 1 > qrow1) sacc[j][3] = -1e30f;
            }
        }

        float mx0 = -1e30f, mx1 = -1e30f;
        #pragma unroll
        for (int j = 0; j < 8; ++j) {
            mx0 = fmaxf(mx0, fmaxf(sacc[j][0], sacc[j][1]));
            mx1 = fmaxf(mx1, fmaxf(sacc[j][2], sacc[j][3]));
        }
        #pragma unroll
        for (int o = 1; o < 4; o <<= 1) {
            mx0 = fmaxf(mx0, __shfl_xor_sync(0xffffffffu, mx0, o));
            mx1 = fmaxf(mx1, __shfl_xor_sync(0xffffffffu, mx1, o));
        }
        const float mn0 = fmaxf(m0, mx0), mn1 = fmaxf(m1, mx1);
        const float e0 = __expf(m0 - mn0), e1 = __expf(m1 - mn1);
        m0 = mn0; m1 = mn1;
        float rs0 = 0.f, rs1 = 0.f;
        #pragma unroll
        for (int j = 0; j < 8; ++j) {
            sacc[j][0] = __expf(sacc[j][0] - mn0); rs0 += sacc[j][0];
            sacc[j][1] = __expf(sacc[j][1] - mn0); rs0 += sacc[j][1];
            sacc[j][2] = __expf(sacc[j][2] - mn1); rs1 += sacc[j][2];
            sacc[j][3] = __expf(sacc[j][3] - mn1); rs1 += sacc[j][3];
        }
        #pragma unroll
        for (int o = 1; o < 4; o <<= 1) {
            rs0 += __shfl_xor_sync(0xffffffffu, rs0, o);
            rs1 += __shfl_xor_sync(0xffffffffu, rs1, o);
        }
        l0 = l0 * e0 + rs0;
        l1 = l1 * e1 + rs1;
        #pragma unroll
        for (int t = 0; t < 16; t++) {
            oacc[t][0] *= e0; oacc[t][1] *= e0;
            oacc[t][2] *= e1; oacc[t][3] *= e1;
        }

        #pragma unroll
        for (int c = 0; c < 4; ++c) {
            uint32_t pah[4];
            pah[0] = pack_h(sacc[2*c][0],   sacc[2*c][1]);
            pah[1] = pack_h(sacc[2*c][2],   sacc[2*c][3]);
            pah[2] = pack_h(sacc[2*c+1][0], sacc[2*c+1][1]);
            pah[3] = pack_h(sacc[2*c+1][2], sacc[2*c+1][3]);
            #pragma unroll
            for (int tp = 0; tp < 8; ++tp) {
                uint32_t rvh[4];
                ldm_x4_t(rvh, sb + ATILE + vb_off + (c * 16 * AST + tp * 16) * 2);
                mma_f16(oacc[2*tp],   pah, &rvh[0]);
                mma_f16(oacc[2*tp+1], pah, &rvh[2]);
            }
        }
        __syncthreads();
    }

    const float inv0 = 1.0f / l0, inv1 = 1.0f / l1;
    const size_t ob0 = ((size_t)b * SS + qrow0) * HID + h * HD;
    const size_t ob1 = ((size_t)b * SS + qrow1) * HID + h * HD;
    #pragma unroll
    for (int t = 0; t < 16; ++t) {
        const int d = t * 8 + (lane & 3) * 2;
        *(uint32_t*)(ctx + ob0 + d) = pack_h(oacc[t][0] * inv0, oacc[t][1] * inv0);
        *(uint32_t*)(ctx + ob1 + d) = pack_h(oacc[t][2] * inv1, oacc[t][3] * inv1);
    }
}

// ---------------- launch (dense stream DAG; Wo last) ----------------
extern "C" void kernel_launch(void* const* d_in, const int* in_sizes, int n_in,
                              void* d_out, int out_size) {
    const float* hid   = (const float*)d_in[0];
    const float* ln1g  = (const float*)d_in[1];
    const float* ln1b  = (const float*)d_in[2];
    const float* ln2g  = (const float*)d_in[3];
    const float* ln2b  = (const float*)d_in[4];
    const float* Wqkv  = (const float*)d_in[5];
    const float* bqkv  = (const float*)d_in[6];
    const float* Wo    = (const float*)d_in[7];
    const float* bo    = (const float*)d_in[8];
    const float* Wfc   = (const float*)d_in[9];
    const float* bfc   = (const float*)d_in[10];
    const float* Wproj = (const float*)d_in[11];
    const float* bproj = (const float*)d_in[12];
    float* out = (float*)d_out;

    float *rope;
    hf *ln1, *ln2, *ctx, *fc, *Q, *K, *V;
    hf *wqkv, *wo, *wfc, *wproj;
    cudaGetSymbolAddress((void**)&rope, g_rope);
    cudaGetSymbolAddress((void**)&ln1, g_ln1);
    cudaGetSymbolAddress((void**)&ln2, g_ln2);
    cudaGetSymbolAddress((void**)&ctx, g_ctx);
    cudaGetSymbolAddress((void**)&fc, g_fc);
    cudaGetSymbolAddress((void**)&Q, g_Q);
    cudaGetSymbolAddress((void**)&K, g_K);
    cudaGetSymbolAddress((void**)&V, g_V);
    cudaGetSymbolAddress((void**)&wqkv, g_wqkv);
    cudaGetSymbolAddress((void**)&wo, g_wo);
    cudaGetSymbolAddress((void**)&wfc, g_wfc);
    cudaGetSymbolAddress((void**)&wproj, g_wproj);

    cudaFuncSetAttribute(mma_gemm_h<1>, cudaFuncAttributeMaxDynamicSharedMemorySize, H_SMEM);
    cudaFuncSetAttribute(mma_gemm_h<3>, cudaFuncAttributeMaxDynamicSharedMemorySize, H_SMEM);
    cudaFuncSetAttribute(mma_gemm_h<4>, cudaFuncAttributeMaxDynamicSharedMemorySize, H_SMEM);
    cudaFuncSetAttribute(attn_mma_kernel, cudaFuncAttributeMaxDynamicSharedMemorySize, A_SMEM);

    static cudaStream_t sB = nullptr, sC = nullptr;
    static cudaEvent_t evRoot = nullptr, evLn = nullptr, evWq = nullptr,
                       evWo = nullptr, evWp = nullptr, evPROJ = nullptr;
    if (!sB) {
        cudaStreamCreateWithFlags(&sB, cudaStreamNonBlocking);
        cudaStreamCreateWithFlags(&sC, cudaStreamNonBlocking);
        cudaEventCreateWithFlags(&evRoot, cudaEventDisableTiming);
        cudaEventCreateWithFlags(&evLn,   cudaEventDisableTiming);
        cudaEventCreateWithFlags(&evWq,   cudaEventDisableTiming);
        cudaEventCreateWithFlags(&evWo,   cudaEventDisableTiming);
        cudaEventCreateWithFlags(&evWp,   cudaEventDisableTiming);
        cudaEventCreateWithFlags(&evPROJ, cudaEventDisableTiming);
    }

    cudaEventRecord(evRoot, 0);
    cudaStreamWaitEvent(sB, evRoot, 0);
    cudaStreamWaitEvent(sC, evRoot, 0);

    // --- stream C: Wqkv, Wo, Wproj conversions ---
    wconv_h_kernel<<<dim3(3 * HID / 64, HID / 64), 256, 0, sC>>>(Wqkv, wqkv, HID, 3 * HID);
    cudaEventRecord(evWq, sC);
    wconv_h_kernel<<<dim3(HID / 64, HID / 64), 256, 0, sC>>>(Wo, wo, HID, HID);
    cudaEventRecord(evWo, sC);
    wconv_h_kernel<<<dim3(HID / 64, FF / 64), 256, 0, sC>>>(Wproj, wproj, FF, HID);
    cudaEventRecord(evWp, sC);

    // --- stream B: Wfc conversion, FC gemm, PROJ gemm ---
    wconv_h_kernel<<<dim3(FF / 64, HID / 64), 256, 0, sB>>>(Wfc, wfc, HID, FF);

    // --- origin: ln (+rope table) ---
    ln_kernel<<<NTOK / 2, 512>>>(hid, ln1g, ln1b, ln2g, ln2b, ln1, ln2, rope);
    cudaEventRecord(evLn, 0);

    // stream B: FC = gelu(ln2 @ W_fc + b_fc)
    cudaStreamWaitEvent(sB, evLn, 0);
    mma_gemm_h<1><<<16 * (FF / 128), 512, H_SMEM, sB>>>(
        ln2, wfc, bfc, nullptr, nullptr,
        nullptr, fc, nullptr, nullptr, FF, HID);
    // stream B: out = fc @ W_proj + b_proj + hid
    cudaStreamWaitEvent(sB, evWp, 0);
    mma_gemm_h<4><<<16 * (HID / 128), 512, H_SMEM, sB>>>(
        fc, wproj, bproj, hid, nullptr,
        out, nullptr, nullptr, nullptr, HID, FF);
    cudaEventRecord(evPROJ, sB);

    // origin: QKV gemm + fused bias/RoPE/scale/head-transpose
    cudaStreamWaitEvent(0, evWq, 0);
    mma_gemm_h<3><<<16 * (3 * HID / 128), 512, H_SMEM>>>(
        ln1, wqkv, bqkv, nullptr, rope,
        nullptr, Q, K, V, 3 * HID, HID);

    // origin: attention (pure fp16)
    attn_mma_kernel<<<dim3(SS / 128, BB * HH), 256, A_SMEM>>>(Q, K, V, ctx);

    // origin: out += ctx @ W_o + b_o
    cudaStreamWaitEvent(0, evWo, 0);
    cudaStreamWaitEvent(0, evPROJ, 0);
    mma_gemm_h<4><<<16 * (HID / 128), 512, H_SMEM>>>(
        ctx, wo, bo, out, nullptr,
        out, nullptr, nullptr, nullptr, HID, HID);
}

// round 17
// speedup vs baseline: 1.0483x; 1.0287x over previous
#include <cuda_runtime.h>
#include <cuda_fp16.h>
#include <cstdint>

// Problem constants
#define BB 2
#define SS 2048
#define HH 16
#define HD 128
#define HID 2048
#define FF 8192
#define NTOK 4096

typedef __half hf;

// ---------------- scratch (device globals; no allocation allowed) ----------
__device__ float g_rope[SS * 16 * 2];
__device__ hf g_ln1[(size_t)NTOK * HID];
__device__ hf g_ln2[(size_t)NTOK * HID];
__device__ hf g_ctx[(size_t)NTOK * HID];
__device__ hf g_fc[(size_t)NTOK * FF];
__device__ hf g_Q[(size_t)NTOK * HID];
__device__ hf g_K[(size_t)NTOK * HID];
__device__ hf g_V[(size_t)NTOK * HID];
__device__ hf g_wqkv[(size_t)3 * HID * HID];
__device__ hf g_wo[(size_t)HID * HID];
__device__ hf g_wfc[(size_t)FF * HID];
__device__ hf g_wproj[(size_t)HID * FF];

// ---------------- helpers ----------------
__device__ __forceinline__ uint32_t smem_u32(const void* p) {
    uint32_t a;
    asm("{ .reg .u64 t; cvta.to.shared.u64 t, %1; cvt.u32.u64 %0, t; }" : "=r"(a) : "l"(p));
    return a;
}
#define CP16(dst, src) \
    asm volatile("cp.async.cg.shared.global [%0], [%1], 16;" :: "r"(dst), "l"(src) : "memory")
#define CP_COMMIT() asm volatile("cp.async.commit_group;" ::: "memory")
#define CP_WAIT1()  asm volatile("cp.async.wait_group 1;" ::: "memory")
#define CP_WAIT0()  asm volatile("cp.async.wait_group 0;" ::: "memory")

__device__ __forceinline__ void ldm_x4(uint32_t* r, uint32_t addr) {
    asm volatile("ldmatrix.sync.aligned.m8n8.x4.shared.b16 {%0,%1,%2,%3}, [%4];"
                 : "=r"(r[0]), "=r"(r[1]), "=r"(r[2]), "=r"(r[3]) : "r"(addr));
}
__device__ __forceinline__ void ldm_x4_t(uint32_t* r, uint32_t addr) {
    asm volatile("ldmatrix.sync.aligned.m8n8.x4.trans.shared.b16 {%0,%1,%2,%3}, [%4];"
                 : "=r"(r[0]), "=r"(r[1]), "=r"(r[2]), "=r"(r[3]) : "r"(addr));
}
__device__ __forceinline__ void mma_f16(float* c, const uint32_t* a, const uint32_t* b) {
    asm volatile("mma.sync.aligned.m16n8k16.row.col.f32.f16.f16.f32 "
                 "{%0,%1,%2,%3},{%4,%5,%6,%7},{%8,%9},{%0,%1,%2,%3};"
                 : "+f"(c[0]), "+f"(c[1]), "+f"(c[2]), "+f"(c[3])
                 : "r"(a[0]), "r"(a[1]), "r"(a[2]), "r"(a[3]), "r"(b[0]), "r"(b[1]));
}
__device__ __forceinline__ uint32_t pack_h(float a, float b) {
    __half2 hv;
    hv.x = __float2half_rn(a);
    hv.y = __float2half_rn(b);
    return *(uint32_t*)&hv;
}
__device__ __forceinline__ float gelu_exact(float v) {
    return 0.5f * v * (1.0f + erff(v * 0.70710678118654752f));
}

// ------- fused double layernorm (2 rows/block) + RoPE table ----------------
__global__ void ln_kernel(const float* __restrict__ x,
                          const float* __restrict__ g1, const float* __restrict__ b1,
                          const float* __restrict__ g2, const float* __restrict__ b2,
                          hf* __restrict__ o1, hf* __restrict__ o2,
                          float* __restrict__ rtab) {
    __shared__ float redS[16];
    __shared__ float redQ[16];
    const int t = threadIdx.x;             // 512
    const int half_ = t >> 8;
    const int tt = t & 255;
    const int row = blockIdx.x * 2 + half_;

    if (blockIdx.x < 64) {
        const int i = blockIdx.x * 512 + t;
        const int s = i >> 4, fi = i & 15;
        const float inv = powf(10000.0f, -(float)fi * (1.0f / 16.0f));
        float sn, cs;
        sincosf((float)s * inv, &sn, &cs);
        rtab[i * 2]     = cs;
        rtab[i * 2 + 1] = sn;
    }

    const float* xr = x + (size_t)row * HID;
    float4 a = *(const float4*)(xr + tt * 8);
    float4 b = *(const float4*)(xr + tt * 8 + 4);
    float s  = a.x + a.y + a.z + a.w + b.x + b.y + b.z + b.w;
    float ss = a.x*a.x + a.y*a.y + a.z*a.z + a.w*a.w
             + b.x*b.x + b.y*b.y + b.z*b.z + b.w*b.w;
    #pragma unroll
    for (int o = 16; o; o >>= 1) {
        s  += __shfl_xor_sync(0xffffffffu, s,  o);
        ss += __shfl_xor_sync(0xffffffffu, ss, o);
    }
    if ((t & 31) == 0) { redS[t >> 5] = s; redQ[t >> 5] = ss; }
    __syncthreads();
    s = 0.f; ss = 0.f;
    #pragma unroll
    for (int i = 0; i < 8; i++) { s += redS[half_ * 8 + i]; ss += redQ[half_ * 8 + i]; }
    const float mu  = s * (1.0f / HID);
    const float var = ss * (1.0f / HID) - mu * mu;
    const float rs  = rsqrtf(var + 1e-5f);

    float vals[8] = {a.x,a.y,a.z,a.w,b.x,b.y,b.z,b.w};
    __align__(16) hf h1[8], h2[8];
    #pragma unroll
    for (int q = 0; q < 8; q++) {
        const int col = tt * 8 + q;
        const float xn = (vals[q] - mu) * rs;
        h1[q] = __float2half_rn(xn * g1[col] + b1[col]);
        h2[q] = __float2half_rn(xn * g2[col] + b2[col]);
    }
    const size_t off = (size_t)row * HID + tt * 8;
    *(uint4*)(o1 + off) = *(uint4*)h1;
    *(uint4*)(o2 + off) = *(uint4*)h2;
}

// ------- weight convert + transpose (fp16): W[K][N] -> T[N][K] -------------
__global__ void wconv_h_kernel(const float* __restrict__ W, hf* __restrict__ Th,
                               int K, int N) {
    __shared__ float tile[64][65];
    const int n0 = blockIdx.x * 64, k0 = blockIdx.y * 64;
    const int tid = threadIdx.x;           // 256
    {
        const int r = tid >> 4, c = (tid & 15) * 4;
        #pragma unroll
        for (int i = 0; i < 4; i++) {
            const float4 v = *(const float4*)(W + (size_t)(k0 + r + 16 * i) * N + n0 + c);
            tile[r + 16 * i][c]     = v.x;
            tile[r + 16 * i][c + 1] = v.y;
            tile[r + 16 * i][c + 2] = v.z;
            tile[r + 16 * i][c + 3] = v.w;
        }
    }
    __syncthreads();
    #pragma unroll
    for (int it = 0; it < 2; ++it) {
        const int idx = tid + it * 256;
        const int n = idx >> 3, kc = (idx & 7) * 8;
        __align__(16) hf h[8];
        #pragma unroll
        for (int j = 0; j < 8; j++)
            h[j] = __float2half_rn(tile[kc + j][n]);
        const size_t o = (size_t)(n0 + n) * K + k0 + kc;
        *(uint4*)(Th + o) = *(uint4*)h;
    }
}

// --- fp16 1-pass GEMM, CTA 128x128, BK=64, 256 thr, 2 CTAs/SM, 2-stage -----
#define ROWP   72
#define A_ARR  18432u
#define B_ARR  18432u
#define H_STG  (A_ARR + B_ARR)          // 36864
#define H_SMEM (2u * H_STG)             // 73728

// EPI: 1 gelu(+bias)->fp16 | 3 qkv fused | 4 +bias+add1->f32
template <int EPI>
__global__ void __launch_bounds__(256, 2) mma_gemm_h(
    const hf* __restrict__ A, const hf* __restrict__ B,
    const float* __restrict__ bias,
    const float* __restrict__ add1,
    const float* __restrict__ rtab,
    float* __restrict__ Cf, hf* __restrict__ Ch,
    hf* __restrict__ Ko, hf* __restrict__ Vo,
    int N, int K) {
    extern __shared__ char sm[];
    const uint32_t smb = smem_u32(sm);
    const int tid = threadIdx.x;
    const int lane = tid & 31;
    const int warp = tid >> 5;
    const int wm = warp >> 2;          // 2 warps along M (64 rows each)
    const int wn = warp & 3;           // 4 warps along N (32 cols each)

    const int Nt = N >> 7;
    const int pid = blockIdx.x;        // Mt = 32, divisible by 8
    const int mt = (pid / (8 * Nt)) * 8 + (pid & 7);
    const int nt = (pid % (8 * Nt)) >> 3;

    const size_t arow0 = (size_t)mt * 128;
    const size_t brow0 = (size_t)nt * 128;
    const hf* pa = A + arow0 * K;
    const hf* pb = B + brow0 * K;
    const int nch = K >> 6;

    const uint32_t aoff = ((wm * 64 + (lane & 15)) * ROWP + (lane >> 4) * 8) * 2;
    const uint32_t boff = ((wn * 32 + (lane & 7) + ((lane >> 4) & 1) * 8) * ROWP
                           + ((lane >> 3) & 1) * 8) * 2;

    float acc[4][4][4];
    #pragma unroll
    for (int m = 0; m < 4; m++)
        #pragma unroll
        for (int n = 0; n < 4; n++)
            #pragma unroll
            for (int q = 0; q < 4; q++) acc[m][n][q] = 0.f;

    auto load_stage = [&](int stg, int k0) {
        const uint32_t sb = smb + (uint32_t)stg * H_STG;
        #pragma unroll
        for (int i = 0; i < 4; ++i) {       // A: 1024 16B chunks (128r x 8c)
            const int id = tid + i * 256;
            const int row = id >> 3, cc = id & 7;
            CP16(sb + (uint32_t)(row * ROWP + cc * 8) * 2,
                 pa + (size_t)row * K + k0 + cc * 8);
        }
        #pragma unroll
        for (int i = 0; i < 4; ++i) {       // B: 1024 chunks
            const int id = tid + i * 256;
            const int row = id >> 3, cc = id & 7;
            CP16(sb + A_ARR + (uint32_t)(row * ROWP + cc * 8) * 2,
                 pb + (size_t)row * K + k0 + cc * 8);
        }
    };

    load_stage(0, 0);
    CP_COMMIT();

    for (int c = 0; c < nch; ++c) {
        CP_WAIT0();
        __syncthreads();
        if (c + 1 < nch) {
            load_stage((c + 1) & 1, (c + 1) << 6);
            CP_COMMIT();
        }
        const uint32_t sb = smb + (uint32_t)(c & 1) * H_STG;
        #pragma unroll
        for (int ks = 0; ks < 4; ++ks) {
            const uint32_t kb = ks * 32;
            uint32_t ah[4][4], bh[2][4];
            #pragma unroll
            for (int i = 0; i < 4; ++i)
                ldm_x4(ah[i], sb + aoff + kb + i * 16 * ROWP * 2);
            #pragma unroll
            for (int t2 = 0; t2 < 2; ++t2)
                ldm_x4(bh[t2], sb + A_ARR + boff + kb + t2 * 16 * ROWP * 2);
            #pragma unroll
            for (int m = 0; m < 4; ++m)
                #pragma unroll
                for (int n = 0; n < 4; ++n)
                    mma_f16(acc[m][n], ah[m], &bh[n >> 1][(n & 1) * 2]);
        }
    }

    // ---------------- epilogue ----------------
    const int row_base = mt * 128 + wm * 64;
    const int col_base = nt * 128 + wn * 32;

    if (EPI == 3) {
        // qkv: bias, RoPE (d<32 of q/k), q-scale -> head-major fp16
        const int hh2 = col_base / 384;
        const int sub0 = col_base % 384;
        const int sect = sub0 >> 7;            // 0=q 1=k 2=v
        const int dbase = sub0 & 127;
        const bool ropeW = (dbase == 0) && (sect < 2);
        const float qsc = (sect == 0) ? 0.08838834764831845f : 1.0f;
        hf* Oo = (sect == 0) ? Ch : (sect == 1) ? Ko : Vo;
        #pragma unroll
        for (int m = 0; m < 4; ++m) {
            const int r0 = row_base + m * 16 + (lane >> 2);
            const int r1 = r0 + 8;
            const int bb2 = r0 >> 11;
            const int s0 = r0 & (SS - 1), s1 = r1 & (SS - 1);
            float v[4][4];
            #pragma unroll
            for (int n = 0; n < 4; ++n) {
                const int cc = col_base + n * 8 + (lane & 3) * 2;
                const float b0 = bias[cc], b1 = bias[cc + 1];
                v[n][0] = acc[m][n][0] + b0; v[n][1] = acc[m][n][1] + b1;
                v[n][2] = acc[m][n][2] + b0; v[n][3] = acc[m][n][3] + b1;
            }
            if (ropeW) {
                float rp[4][4];
                #pragma unroll
                for (int n = 0; n < 4; ++n) {
                    const int dl = n * 8 + (lane & 3) * 2;   // 0..30 even
                    const bool first = dl < 16;
                    const int np = first ? n + 2 : n - 2;
                    const float sign = first ? -1.0f : 1.0f;
                    const int fi0 = dl & 15, fi1 = (dl + 1) & 15;
                    const float2 c00 = *(const float2*)(rtab + (s0 * 16 + fi0) * 2);
                    const float2 c01 = *(const float2*)(rtab + (s0 * 16 + fi1) * 2);
                    const float2 c10 = *(const float2*)(rtab + (s1 * 16 + fi0) * 2);
                    const float2 c11 = *(const float2*)(rtab + (s1 * 16 + fi1) * 2);
                    rp[n][0] = v[n][0] * c00.x + sign * v[np][0] * c00.y;
                    rp[n][1] = v[n][1] * c01.x + sign * v[np][1] * c01.y;
                    rp[n][2] = v[n][2] * c10.x + sign * v[np][2] * c10.y;
                    rp[n][3] = v[n][3] * c11.x + sign * v[np][3] * c11.y;
                }
                #pragma unroll
                for (int n = 0; n < 4; ++n)
                    #pragma unroll
                    for (int q = 0; q < 4; ++q) v[n][q] = rp[n][q];
            }
            const size_t base0 = (((size_t)bb2 * HH + hh2) * SS + s0) * HD;
            const size_t base1 = (((size_t)bb2 * HH + hh2) * SS + s1) * HD;
            #pragma unroll
            for (int n = 0; n < 4; ++n) {
                const int d = dbase + n * 8 + (lane & 3) * 2;
                *(uint32_t*)(Oo + base0 + d) = pack_h(v[n][0] * qsc, v[n][1] * qsc);
                *(uint32_t*)(Oo + base1 + d) = pack_h(v[n][2] * qsc, v[n][3] * qsc);
            }
        }
        return;
    }

    #pragma unroll
    for (int m = 0; m < 4; ++m) {
        const int r0 = row_base + m * 16 + (lane >> 2);
        #pragma unroll
        for (int n = 0; n < 4; ++n) {
            const int cc = col_base + n * 8 + (lane & 3) * 2;
            const float b0 = bias[cc], b1 = bias[cc + 1];
            float v0 = acc[m][n][0] + b0, v1 = acc[m][n][1] + b1;
            float v2 = acc[m][n][2] + b0, v3 = acc[m][n][3] + b1;
            const size_t off0 = (size_t)r0 * N + cc;
            const size_t off1 = (size_t)(r0 + 8) * N + cc;
            if (EPI == 1) {
                *(uint32_t*)(Ch + off0) = pack_h(gelu_exact(v0), gelu_exact(v1));
                *(uint32_t*)(Ch + off1) = pack_h(gelu_exact(v2), gelu_exact(v3));
            } else {
                const float2 x0 = *(const float2*)(add1 + off0);
                const float2 x1 = *(const float2*)(add1 + off1);
                v0 += x0.x; v1 += x0.y;
                v2 += x1.x; v3 += x1.y;
                *(float2*)(Cf + off0) = make_float2(v0, v1);
                *(float2*)(Cf + off1) = make_float2(v2, v3);
            }
        }
    }
}

// ---------- causal flash attention, pure fp16, BQ=128 ----------------------
#define AST   136
#define ATILE (64 * AST * 2)
#define AQ_0  0
#define ASTAGE0 (2 * ATILE)              // Q is 128 rows = 2*ATILE
#define ASTG_B  (2 * ATILE)              // K, V
#define A_SMEM  (2 * ATILE + 2 * ASTG_B) // 104448

__global__ void __launch_bounds__(256, 1) attn_mma_kernel(
    const hf* __restrict__ Q, const hf* __restrict__ Kg,
    const hf* __restrict__ Vg,
    hf* __restrict__ ctx) {
    extern __shared__ char sm[];
    const uint32_t smb = smem_u32(sm);
    const int qt = gridDim.x - 1 - blockIdx.x;
    const int bhid = blockIdx.y;
    const int b = bhid >> 4, h = bhid & 15;
    const int tid = threadIdx.x;
    const int lane = tid & 31;
    const int w = tid >> 5;

    const size_t headbase = (size_t)bhid * SS * HD;

    auto ldq = [&]() {
        const size_t gb = headbase + (size_t)qt * 128 * HD;
        #pragma unroll
        for (int i = 0; i < 8; i++) {
            const int c = tid + i * 256;
            const int row = c >> 4, ch = c & 15;
            CP16(smb + AQ_0 + row * (AST * 2) + ch * 16,
                 Q + gb + (size_t)row * HD + ch * 8);
        }
    };
    auto ldkv = [&](int kt, int stg) {
        const uint32_t sb = smb + ASTAGE0 + (uint32_t)stg * ASTG_B;
        const size_t gb = headbase + (size_t)kt * 64 * HD;
        #pragma unroll
        for (int i = 0; i < 4; i++) {
            const int c = tid + i * 256;
            const int row = c >> 4, ch = c & 15;
            const uint32_t so = row * (AST * 2) + ch * 16;
            const size_t go = gb + (size_t)row * HD + ch * 8;
            CP16(sb + so,         Kg + go);
            CP16(sb + ATILE + so, Vg + go);
        }
    };

    const uint32_t qa_off = ((w * 16 + (lane & 15)) * AST + (lane >> 4) * 8) * 2;
    const int lm = lane >> 3, li = lane & 7;
    const uint32_t kb_off = (((lm >> 1) * 8 + li) * AST + (lm & 1) * 8) * 2;
    const uint32_t vb_off = (((lm & 1) * 8 + li) * AST + (lm >> 1) * 8) * 2;

    float oacc[16][4];
    #pragma unroll
    for (int t = 0; t < 16; t++)
        #pragma unroll
        for (int q = 0; q < 4; q++) oacc[t][q] = 0.f;
    float m0 = -1e30f, m1 = -1e30f, l0 = 0.f, l1 = 0.f;
    const int qrow0 = qt * 128 + w * 16 + (lane >> 2);
    const int qrow1 = qrow0 + 8;
    const int nkt = 2 * qt + 2;

    ldq();
    ldkv(0, 0);
    CP_COMMIT();

    for (int kt = 0; kt < nkt; ++kt) {
        if (kt + 1 < nkt) {
            ldkv(kt + 1, (kt + 1) & 1);
            CP_COMMIT();
            CP_WAIT1();
        } else {
            CP_WAIT0();
        }
        __syncthreads();
        const uint32_t sb = smb + ASTAGE0 + (uint32_t)(kt & 1) * ASTG_B;

        float sacc[8][4];
        #pragma unroll
        for (int j = 0; j < 8; j++)
            #pragma unroll
            for (int q = 0; q < 4; q++) sacc[j][q] = 0.f;

        #pragma unroll
        for (int ks = 0; ks < 8; ++ks) {
            uint32_t ah[4], kfh[8][2];
            ldm_x4(ah, smb + AQ_0 + qa_off + ks * 32);
            #pragma unroll
            for (int jp = 0; jp < 4; ++jp) {
                uint32_t r[4];
                ldm_x4(r, sb + kb_off + (jp * 16 * AST + ks * 16) * 2);
                kfh[2*jp][0] = r[0]; kfh[2*jp][1] = r[1];
                kfh[2*jp+1][0] = r[2]; kfh[2*jp+1][1] = r[3];
            }
            #pragma unroll
            for (int j = 0; j < 8; ++j) mma_f16(sacc[j], ah, kfh[j]);
        }

        if (kt >= 2 * qt) {
            #pragma unroll
            for (int j = 0; j < 8; ++j) {
                const int c0 = kt * 64 + j * 8 + (lane & 3) * 2;
                if (c0     > qrow0) sacc[j][0] = -1e30f;
                if (c0 + 1 > qrow0) sacc[j][1] = -1e30f;
                if (c0     > qrow1) sacc[j][2] = -1e30f;
                if (c0 + 1 > qrow1) sacc[j][3] = -1e30f;
            }
        }

        float mx0 = -1e30f, mx1 = -1e30f;
        #pragma unroll
        for (int j = 0; j < 8; ++j) {
            mx0 = fmaxf(mx0, fmaxf(sacc[j][0], sacc[j][1]));
            mx1 = fmaxf(mx1, fmaxf(sacc[j][2], sacc[j][3]));
        }
        #pragma unroll
        for (int o = 1; o < 4; o <<= 1) {
            mx0 = fmaxf(mx0, __shfl_xor_sync(0xffffffffu, mx0, o));
            mx1 = fmaxf(mx1, __shfl_xor_sync(0xffffffffu, mx1, o));
        }
        const float mn0 = fmaxf(m0, mx0), mn1 = fmaxf(m1, mx1);
        const float e0 = __expf(m0 - mn0), e1 = __expf(m1 - mn1);
        m0 = mn0; m1 = mn1;
        float rs0 = 0.f, rs1 = 0.f;
        #pragma unroll
        for (int j = 0; j < 8; ++j) {
            sacc[j][0] = __expf(sacc[j][0] - mn0); rs0 += sacc[j][0];
            sacc[j][1] = __expf(sacc[j][1] - mn0); rs0 += sacc[j][1];
            sacc[j][2] = __expf(sacc[j][2] - mn1); rs1 += sacc[j][2];
            sacc[j][3] = __expf(sacc[j][3] - mn1); rs1 += sacc[j][3];
        }
        #pragma unroll
        for (int o = 1; o < 4; o <<= 1) {
            rs0 += __shfl_xor_sync(0xffffffffu, rs0, o);
            rs1 += __shfl_xor_sync(0xffffffffu, rs1, o);
        }
        l0 = l0 * e0 + rs0;
        l1 = l1 * e1 + rs1;
        #pragma unroll
        for (int t = 0; t < 16; t++) {
            oacc[t][0] *= e0; oacc[t][1] *= e0;
            oacc[t][2] *= e1; oacc[t][3] *= e1;
        }

        #pragma unroll
        for (int c = 0; c < 4; ++c) {
            uint32_t pah[4];
            pah[0] = pack_h(sacc[2*c][0],   sacc[2*c][1]);
            pah[1] = pack_h(sacc[2*c][2],   sacc[2*c][3]);
            pah[2] = pack_h(sacc[2*c+1][0], sacc[2*c+1][1]);
            pah[3] = pack_h(sacc[2*c+1][2], sacc[2*c+1][3]);
            #pragma unroll
            for (int tp = 0; tp < 8; ++tp) {
                uint32_t rvh[4];
                ldm_x4_t(rvh, sb + ATILE + vb_off + (c * 16 * AST + tp * 16) * 2);
                mma_f16(oacc[2*tp],   pah, &rvh[0]);
                mma_f16(oacc[2*tp+1], pah, &rvh[2]);
            }
        }
        __syncthreads();
    }

    const float inv0 = 1.0f / l0, inv1 = 1.0f / l1;
    const size_t ob0 = ((size_t)b * SS + qrow0) * HID + h * HD;
    const size_t ob1 = ((size_t)b * SS + qrow1) * HID + h * HD;
    #pragma unroll
    for (int t = 0; t < 16; ++t) {
        const int d = t * 8 + (lane & 3) * 2;
        *(uint32_t*)(ctx + ob0 + d) = pack_h(oacc[t][0] * inv0, oacc[t][1] * inv0);
        *(uint32_t*)(ctx + ob1 + d) = pack_h(oacc[t][2] * inv1, oacc[t][3] * inv1);
    }
}

// ---------------- launch (dense stream DAG; Wo last) ----------------
extern "C" void kernel_launch(void* const* d_in, const int* in_sizes, int n_in,
                              void* d_out, int out_size) {
    const float* hid   = (const float*)d_in[0];
    const float* ln1g  = (const float*)d_in[1];
    const float* ln1b  = (const float*)d_in[2];
    const float* ln2g  = (const float*)d_in[3];
    const float* ln2b  = (const float*)d_in[4];
    const float* Wqkv  = (const float*)d_in[5];
    const float* bqkv  = (const float*)d_in[6];
    const float* Wo    = (const float*)d_in[7];
    const float* bo    = (const float*)d_in[8];
    const float* Wfc   = (const float*)d_in[9];
    const float* bfc   = (const float*)d_in[10];
    const float* Wproj = (const float*)d_in[11];
    const float* bproj = (const float*)d_in[12];
    float* out = (float*)d_out;

    float *rope;
    hf *ln1, *ln2, *ctx, *fc, *Q, *K, *V;
    hf *wqkv, *wo, *wfc, *wproj;
    cudaGetSymbolAddress((void**)&rope, g_rope);
    cudaGetSymbolAddress((void**)&ln1, g_ln1);
    cudaGetSymbolAddress((void**)&ln2, g_ln2);
    cudaGetSymbolAddress((void**)&ctx, g_ctx);
    cudaGetSymbolAddress((void**)&fc, g_fc);
    cudaGetSymbolAddress((void**)&Q, g_Q);
    cudaGetSymbolAddress((void**)&K, g_K);
    cudaGetSymbolAddress((void**)&V, g_V);
    cudaGetSymbolAddress((void**)&wqkv, g_wqkv);
    cudaGetSymbolAddress((void**)&wo, g_wo);
    cudaGetSymbolAddress((void**)&wfc, g_wfc);
    cudaGetSymbolAddress((void**)&wproj, g_wproj);

    cudaFuncSetAttribute(mma_gemm_h<1>, cudaFuncAttributeMaxDynamicSharedMemorySize, H_SMEM);
    cudaFuncSetAttribute(mma_gemm_h<3>, cudaFuncAttributeMaxDynamicSharedMemorySize, H_SMEM);
    cudaFuncSetAttribute(mma_gemm_h<4>, cudaFuncAttributeMaxDynamicSharedMemorySize, H_SMEM);
    cudaFuncSetAttribute(attn_mma_kernel, cudaFuncAttributeMaxDynamicSharedMemorySize, A_SMEM);

    static cudaStream_t sB = nullptr, sC = nullptr;
    static cudaEvent_t evRoot = nullptr, evLn = nullptr, evWq = nullptr,
                       evWo = nullptr, evWp = nullptr, evPROJ = nullptr;
    if (!sB) {
        cudaStreamCreateWithFlags(&sB, cudaStreamNonBlocking);
        cudaStreamCreateWithFlags(&sC, cudaStreamNonBlocking);
        cudaEventCreateWithFlags(&evRoot, cudaEventDisableTiming);
        cudaEventCreateWithFlags(&evLn,   cudaEventDisableTiming);
        cudaEventCreateWithFlags(&evWq,   cudaEventDisableTiming);
        cudaEventCreateWithFlags(&evWo,   cudaEventDisableTiming);
        cudaEventCreateWithFlags(&evWp,   cudaEventDisableTiming);
        cudaEventCreateWithFlags(&evPROJ, cudaEventDisableTiming);
    }

    cudaEventRecord(evRoot, 0);
    cudaStreamWaitEvent(sB, evRoot, 0);
    cudaStreamWaitEvent(sC, evRoot, 0);

    // --- stream C: Wqkv, Wo, Wproj conversions ---
    wconv_h_kernel<<<dim3(3 * HID / 64, HID / 64), 256, 0, sC>>>(Wqkv, wqkv, HID, 3 * HID);
    cudaEventRecord(evWq, sC);
    wconv_h_kernel<<<dim3(HID / 64, HID / 64), 256, 0, sC>>>(Wo, wo, HID, HID);
    cudaEventRecord(evWo, sC);
    wconv_h_kernel<<<dim3(HID / 64, FF / 64), 256, 0, sC>>>(Wproj, wproj, FF, HID);
    cudaEventRecord(evWp, sC);

    // --- stream B: Wfc conversion, FC gemm, PROJ gemm ---
    wconv_h_kernel<<<dim3(FF / 64, HID / 64), 256, 0, sB>>>(Wfc, wfc, HID, FF);

    // --- origin: ln (+rope table) ---
    ln_kernel<<<NTOK / 2, 512>>>(hid, ln1g, ln1b, ln2g, ln2b, ln1, ln2, rope);
    cudaEventRecord(evLn, 0);

    // stream B: FC = gelu(ln2 @ W_fc + b_fc)
    cudaStreamWaitEvent(sB, evLn, 0);
    mma_gemm_h<1><<<32 * (FF / 128), 256, H_SMEM, sB>>>(
        ln2, wfc, bfc, nullptr, nullptr,
        nullptr, fc, nullptr, nullptr, FF, HID);
    // stream B: out = fc @ W_proj + b_proj + hid
    cudaStreamWaitEvent(sB, evWp, 0);
    mma_gemm_h<4><<<32 * (HID / 128), 256, H_SMEM, sB>>>(
        fc, wproj, bproj, hid, nullptr,
        out, nullptr, nullptr, nullptr, HID, FF);
    cudaEventRecord(evPROJ, sB);

    // origin: QKV gemm + fused bias/RoPE/scale/head-transpose
    cudaStreamWaitEvent(0, evWq, 0);
    mma_gemm_h<3><<<32 * (3 * HID / 128), 256, H_SMEM>>>(
        ln1, wqkv, bqkv, nullptr, rope,
        nullptr, Q, K, V, 3 * HID, HID);

    // origin: attention (pure fp16)
    attn_mma_kernel<<<dim3(SS / 128, BB * HH), 256, A_SMEM>>>(Q, K, V, ctx);

    // origin: out += ctx @ W_o + b_o
    cudaStreamWaitEvent(0, evWo, 0);
    cudaStreamWaitEvent(0, evPROJ, 0);
    mma_gemm_h<4><<<32 * (HID / 128), 256, H_SMEM>>>(
        ctx, wo, bo, out, nullptr,
        out, nullptr, nullptr, nullptr, HID, HID);
}